// round 3
// baseline (speedup 1.0000x reference)
#include <cuda_runtime.h>
#include <cstdint>

#define NN   100000
#define NE   1600000
#define HIDV 64
#define ALPHA_C 0.1f
#define COEF_C  0.3f   // (1-ALPHA)/K = 0.9/3

// ---------------- scratch (device globals: no allocation allowed) ----------------
__device__ int   g_is64;             // 1 if edge_index is int64, 0 if int32
__device__ int   g_cnt[NN];          // in-degree (original edges, no self loop)
__device__ int   g_rowptr[NN + 1];   // CSR row pointers by dst
__device__ int   g_cursor[NN];       // scatter cursors
__device__ float g_dinv[NN];         // 1/sqrt(deg+1)
__device__ int   g_part[128];        // scan partials (98 blocks)
__device__ int2  g_sw[NE];           // CSR: {src, w-bits} per edge (sorted by dst)
__device__ float g_h1[NN * HIDV];
__device__ float g_h2[NN * HIDV];
__device__ float g_acc[NN * HIDV];

// ---------------- dtype detection (fused into zero) ----------------
// If edge_index is int64 (values < 100000), every odd 32-bit word is 0.
// If int32, odd words are uniform in [0, 100000): P(zero) = 1e-5 each.
__global__ void k_zero(const int* __restrict__ ei32) {
    int i = blockIdx.x * blockDim.x + threadIdx.x;
    if (i < NN) g_cnt[i] = 0;
    if (i == 0) {
        int zeros = 0;
        #pragma unroll 1
        for (int k = 1; k < 129; k += 2) zeros += (ei32[k] == 0);
        g_is64 = (zeros >= 60) ? 1 : 0;
    }
}

__device__ __forceinline__ int edge_at(const void* ei, long long idx, int is64) {
    if (is64) return (int)((const long long*)ei)[idx];
    return ((const int*)ei)[idx];
}

// ---------------- CSR build ----------------
__global__ void k_hist(const void* __restrict__ ei) {
    int e = blockIdx.x * blockDim.x + threadIdx.x;
    int is64 = g_is64;
    if (e < NE) {
        int dst = edge_at(ei, (long long)NE + e, is64);
        atomicAdd(&g_cnt[dst], 1);
    }
}

// block-local exclusive scan (1024 elems per block), partial sums to g_part
__global__ void k_scan_local() {
    __shared__ int s[1024];
    int tid = threadIdx.x;
    int i = blockIdx.x * 1024 + tid;
    int v = (i < NN) ? g_cnt[i] : 0;
    s[tid] = v;
    __syncthreads();
    #pragma unroll
    for (int off = 1; off < 1024; off <<= 1) {
        int t = (tid >= off) ? s[tid - off] : 0;
        __syncthreads();
        s[tid] += t;
        __syncthreads();
    }
    if (i < NN) g_rowptr[i] = s[tid] - v;   // local exclusive
    if (tid == 1023) g_part[blockIdx.x] = s[1023];
}

__global__ void k_scan_part(int nb) {
    if (threadIdx.x == 0 && blockIdx.x == 0) {
        int run = 0;
        for (int b = 0; b < nb; b++) { int t = g_part[b]; g_part[b] = run; run += t; }
        g_rowptr[NN] = run;   // == NE
    }
}

__global__ void k_finalize() {
    int i = blockIdx.x * blockDim.x + threadIdx.x;
    if (i < NN) {
        int rp = g_rowptr[i] + g_part[i >> 10];
        g_rowptr[i] = rp;
        g_cursor[i] = rp;
        g_dinv[i] = rsqrtf((float)(g_cnt[i] + 1));   // +1 self loop
    }
}

__global__ void k_scatter(const void* __restrict__ ei) {
    int e = blockIdx.x * blockDim.x + threadIdx.x;
    int is64 = g_is64;
    if (e < NE) {
        int src = edge_at(ei, e, is64);
        int dst = edge_at(ei, (long long)NE + e, is64);
        int pos = atomicAdd(&g_cursor[dst], 1);
        float w = g_dinv[src] * g_dinv[dst];
        g_sw[pos] = make_int2(src, __float_as_int(w));
    }
}

// ---------------- propagation: warp per dst row, float2 per lane ----------------
// IN: 0 = g_h1, 1 = g_h2, 2 = x        OUT: 0 = g_h1, 1 = g_h2
template <int IN, int OUT, bool INIT>
__global__ void k_spmm(const float* __restrict__ x) {
    int row  = blockIdx.x * (blockDim.x >> 5) + (threadIdx.x >> 5);
    if (row >= NN) return;
    int lane = threadIdx.x & 31;

    const float2* hin  = (IN == 0) ? (const float2*)g_h1
                       : (IN == 1) ? (const float2*)g_h2
                       :             (const float2*)x;
    float2* hout = (OUT == 0) ? (float2*)g_h1 : (float2*)g_h2;

    int beg = g_rowptr[row];
    int end = g_rowptr[row + 1];
    float dv = g_dinv[row];

    int o = row * 32 + lane;
    float2 self = __ldg(&hin[o]);
    float sx = dv * dv * self.x;   // self-loop term: dinv[i]^2 * h[i]
    float sy = dv * dv * self.y;

    int e = beg;
    // 4x unrolled: batch index loads, then 4 independent 256B gathers in flight
    for (; e + 4 <= end; e += 4) {
        int2 p0 = __ldg(&g_sw[e + 0]);
        int2 p1 = __ldg(&g_sw[e + 1]);
        int2 p2 = __ldg(&g_sw[e + 2]);
        int2 p3 = __ldg(&g_sw[e + 3]);
        float2 v0 = __ldg(&hin[p0.x * 32 + lane]);
        float2 v1 = __ldg(&hin[p1.x * 32 + lane]);
        float2 v2 = __ldg(&hin[p2.x * 32 + lane]);
        float2 v3 = __ldg(&hin[p3.x * 32 + lane]);
        float w0 = __int_as_float(p0.y), w1 = __int_as_float(p1.y);
        float w2 = __int_as_float(p2.y), w3 = __int_as_float(p3.y);
        sx += w0 * v0.x + w1 * v1.x + w2 * v2.x + w3 * v3.x;
        sy += w0 * v0.y + w1 * v1.y + w2 * v2.y + w3 * v3.y;
    }
    for (; e < end; e++) {
        int2 p = __ldg(&g_sw[e]);
        float2 v = __ldg(&hin[p.x * 32 + lane]);
        float w = __int_as_float(p.y);
        sx += w * v.x;
        sy += w * v.y;
    }

    float2 sum; sum.x = sx; sum.y = sy;
    hout[o] = sum;

    float2 a;
    if (INIT) { a.x = ALPHA_C * self.x; a.y = ALPHA_C * self.y; }  // hin == x here
    else      { a = ((float2*)g_acc)[o]; }
    a.x += COEF_C * sx;
    a.y += COEF_C * sy;
    ((float2*)g_acc)[o] = a;
}

// mean conv over original edges, relu(acc) applied on the fly, fused residual+relu
__global__ void k_mean(const float* __restrict__ x, float* __restrict__ out) {
    int row  = blockIdx.x * (blockDim.x >> 5) + (threadIdx.x >> 5);
    if (row >= NN) return;
    int lane = threadIdx.x & 31;

    int beg = g_rowptr[row];
    int end = g_rowptr[row + 1];
    const float2* a2 = (const float2*)g_acc;

    float sx = 0.f, sy = 0.f;
    int e = beg;
    for (; e + 4 <= end; e += 4) {
        int s0 = __ldg(&g_sw[e + 0]).x;
        int s1 = __ldg(&g_sw[e + 1]).x;
        int s2 = __ldg(&g_sw[e + 2]).x;
        int s3 = __ldg(&g_sw[e + 3]).x;
        float2 v0 = __ldg(&a2[s0 * 32 + lane]);
        float2 v1 = __ldg(&a2[s1 * 32 + lane]);
        float2 v2 = __ldg(&a2[s2 * 32 + lane]);
        float2 v3 = __ldg(&a2[s3 * 32 + lane]);
        sx += fmaxf(v0.x, 0.f) + fmaxf(v1.x, 0.f) + fmaxf(v2.x, 0.f) + fmaxf(v3.x, 0.f);
        sy += fmaxf(v0.y, 0.f) + fmaxf(v1.y, 0.f) + fmaxf(v2.y, 0.f) + fmaxf(v3.y, 0.f);
    }
    for (; e < end; e++) {
        int s = __ldg(&g_sw[e]).x;
        float2 v = __ldg(&a2[s * 32 + lane]);
        sx += fmaxf(v.x, 0.f);
        sy += fmaxf(v.y, 0.f);
    }
    float inv = 1.0f / fmaxf((float)(end - beg), 1.0f);

    int o = row * 32 + lane;
    float2 xx = __ldg(&((const float2*)x)[o]);
    float2 r;
    r.x = fmaxf(sx * inv + xx.x, 0.f);
    r.y = fmaxf(sy * inv + xx.y, 0.f);
    ((float2*)out)[o] = r;
}

// ---------------- launch ----------------
extern "C" void kernel_launch(void* const* d_in, const int* in_sizes, int n_in,
                              void* d_out, int out_size) {
    const float* x  = (const float*)d_in[0];
    const void*  ei = (const void*)d_in[1];
    float* out = (float*)d_out;

    k_zero<<<(NN + 255) / 256, 256>>>((const int*)ei);
    k_hist<<<(NE + 255) / 256, 256>>>(ei);
    int nb = (NN + 1023) / 1024;   // 98
    k_scan_local<<<nb, 1024>>>();
    k_scan_part<<<1, 32>>>(nb);
    k_finalize<<<(NN + 255) / 256, 256>>>();
    k_scatter<<<(NE + 255) / 256, 256>>>(ei);

    const int WPB = 8;                       // warps (rows) per block
    int grid = (NN + WPB - 1) / WPB;         // 12500
    // SSG hops: out = 0.1*x + 0.3*(A x + A^2 x + A^3 x)
    k_spmm<2, 0, true ><<<grid, WPB * 32>>>(x);   // x   -> h1, acc = 0.1x + 0.3h1
    k_spmm<0, 1, false><<<grid, WPB * 32>>>(x);   // h1  -> h2, acc += 0.3h2
    k_spmm<1, 0, false><<<grid, WPB * 32>>>(x);   // h2  -> h1, acc += 0.3h1'
    // mean conv on relu(acc) + residual + relu
    k_mean<<<grid, WPB * 32>>>(x, out);
}

// round 4
// speedup vs baseline: 1.2919x; 1.2919x over previous
#include <cuda_runtime.h>
#include <cuda_fp16.h>
#include <cstdint>

#define NN   100000
#define NE   1600000
#define HIDV 64
#define NH2  32                 // half2 elements per row
#define ALPHA_C 0.1f
#define COEF_C  0.3f            // (1-ALPHA)/K = 0.9/3

// ---------------- scratch (device globals: no allocation allowed) ----------------
__device__ int     g_is64;            // 1 if edge_index is int64, 0 if int32
__device__ int     g_cnt[NN];         // in-degree (original edges, no self loop)
__device__ int     g_rowptr[NN + 1];  // CSR row pointers by dst
__device__ int     g_cursor[NN];      // scatter cursors
__device__ float   g_dinv[NN];        // 1/sqrt(deg+1)
__device__ int     g_part[128];       // scan partials (98 blocks)
__device__ int     g_src[NE];         // CSR: source node per edge (sorted by dst)
__device__ float   g_w[NE];           // CSR: dinv[src]*dinv[dst]
__device__ __half2 g_xh [NN * NH2];   // x in fp16
__device__ __half2 g_h1 [NN * NH2];
__device__ __half2 g_h2 [NN * NH2];
__device__ float   g_acc[NN * HIDV];  // fp32 accumulator
__device__ __half2 g_ach[NN * NH2];   // relu(acc) in fp16 (for mean pass)

// ---------------- convert x -> fp16, zero counters, detect edge dtype ----------------
__global__ void k_prep(const float* __restrict__ x, const int* __restrict__ ei32) {
    int i = blockIdx.x * blockDim.x + threadIdx.x;
    if (i < NN * NH2) {
        float2 v = ((const float2*)x)[i];
        g_xh[i] = __float22half2_rn(v);
    }
    if (i < NN) g_cnt[i] = 0;
    if (i == 0) {
        // int64 little-endian with values < 100000 -> every odd 32-bit word is 0
        int zeros = 0;
        #pragma unroll 1
        for (int k = 1; k < 129; k += 2) zeros += (ei32[k] == 0);
        g_is64 = (zeros >= 60) ? 1 : 0;
    }
}

__device__ __forceinline__ int edge_at(const void* ei, long long idx, int is64) {
    if (is64) return (int)((const long long*)ei)[idx];
    return ((const int*)ei)[idx];
}

// ---------------- CSR build ----------------
__global__ void k_hist(const void* __restrict__ ei) {
    int e = blockIdx.x * blockDim.x + threadIdx.x;
    int is64 = g_is64;
    if (e < NE) {
        int dst = edge_at(ei, (long long)NE + e, is64);
        atomicAdd(&g_cnt[dst], 1);
    }
}

__global__ void k_scan_local() {
    __shared__ int s[1024];
    int tid = threadIdx.x;
    int i = blockIdx.x * 1024 + tid;
    int v = (i < NN) ? g_cnt[i] : 0;
    s[tid] = v;
    __syncthreads();
    #pragma unroll
    for (int off = 1; off < 1024; off <<= 1) {
        int t = (tid >= off) ? s[tid - off] : 0;
        __syncthreads();
        s[tid] += t;
        __syncthreads();
    }
    if (i < NN) g_rowptr[i] = s[tid] - v;   // local exclusive
    if (tid == 1023) g_part[blockIdx.x] = s[1023];
}

__global__ void k_scan_part(int nb) {
    if (threadIdx.x == 0 && blockIdx.x == 0) {
        int run = 0;
        for (int b = 0; b < nb; b++) { int t = g_part[b]; g_part[b] = run; run += t; }
        g_rowptr[NN] = run;   // == NE
    }
}

__global__ void k_finalize() {
    int i = blockIdx.x * blockDim.x + threadIdx.x;
    if (i < NN) {
        int rp = g_rowptr[i] + g_part[i >> 10];
        g_rowptr[i] = rp;
        g_cursor[i] = rp;
        g_dinv[i] = rsqrtf((float)(g_cnt[i] + 1));   // +1 self loop
    }
}

__global__ void k_scatter(const void* __restrict__ ei) {
    int e = blockIdx.x * blockDim.x + threadIdx.x;
    int is64 = g_is64;
    if (e < NE) {
        int src = edge_at(ei, e, is64);
        int dst = edge_at(ei, (long long)NE + e, is64);
        int pos = atomicAdd(&g_cursor[dst], 1);
        g_src[pos] = src;
        g_w[pos] = g_dinv[src] * g_dinv[dst];
    }
}

// ---------------- propagation: warp per dst row, half2 per lane ----------------
// IN: 0 = g_h1, 1 = g_h2, 2 = g_xh
// PASS: 1 = init acc (0.1x + 0.3 sum), write h1
//       2 = acc += 0.3 sum, write h2
//       3 = acc += 0.3 sum, relu, write g_ach (half2); no hout
template <int IN, int PASS>
__global__ void k_spmm(const float* __restrict__ x) {
    int row  = blockIdx.x * (blockDim.x >> 5) + (threadIdx.x >> 5);
    if (row >= NN) return;
    int lane = threadIdx.x & 31;

    const __half2* hin = (IN == 0) ? g_h1 : (IN == 1) ? g_h2 : g_xh;

    int beg = g_rowptr[row];
    int end = g_rowptr[row + 1];
    float dv = g_dinv[row];

    int o = row * NH2 + lane;
    float2 self = __half22float2(__ldg(&hin[o]));
    float sx = dv * dv * self.x;   // self-loop: dinv[i]^2 * h[i]
    float sy = dv * dv * self.y;

    // simple loop — cross-warp parallelism hides L2 latency (R2 lesson: don't batch)
    for (int e = beg; e < end; e++) {
        int   s = __ldg(&g_src[e]);
        float w = __ldg(&g_w[e]);
        float2 v = __half22float2(__ldg(&hin[s * NH2 + lane]));
        sx += w * v.x;
        sy += w * v.y;
    }

    if (PASS != 3) {
        __half2* hout = (PASS == 1) ? g_h1 : g_h2;
        hout[o] = __floats2half2_rn(sx, sy);
    }

    float2 a;
    if (PASS == 1) {
        float2 xf = __ldg(&((const float2*)x)[o]);   // fp32 x for acc init
        a.x = ALPHA_C * xf.x; a.y = ALPHA_C * xf.y;
    } else {
        a = ((float2*)g_acc)[o];
    }
    a.x += COEF_C * sx;
    a.y += COEF_C * sy;

    if (PASS == 3) {
        g_ach[o] = __floats2half2_rn(fmaxf(a.x, 0.f), fmaxf(a.y, 0.f));
    } else {
        ((float2*)g_acc)[o] = a;
    }
}

// mean conv over original edges on relu(acc) (already relu'd, fp16), + residual + relu
__global__ void k_mean(const float* __restrict__ x, float* __restrict__ out) {
    int row  = blockIdx.x * (blockDim.x >> 5) + (threadIdx.x >> 5);
    if (row >= NN) return;
    int lane = threadIdx.x & 31;

    int beg = g_rowptr[row];
    int end = g_rowptr[row + 1];

    float sx = 0.f, sy = 0.f;
    for (int e = beg; e < end; e++) {
        int s = __ldg(&g_src[e]);
        float2 v = __half22float2(__ldg(&g_ach[s * NH2 + lane]));
        sx += v.x;
        sy += v.y;
    }
    float inv = 1.0f / fmaxf((float)(end - beg), 1.0f);

    int o = row * NH2 + lane;
    float2 xx = __ldg(&((const float2*)x)[o]);
    float2 r;
    r.x = fmaxf(sx * inv + xx.x, 0.f);
    r.y = fmaxf(sy * inv + xx.y, 0.f);
    ((float2*)out)[o] = r;
}

// ---------------- launch ----------------
extern "C" void kernel_launch(void* const* d_in, const int* in_sizes, int n_in,
                              void* d_out, int out_size) {
    const float* x  = (const float*)d_in[0];
    const void*  ei = (const void*)d_in[1];
    float* out = (float*)d_out;

    k_prep<<<(NN * NH2 + 255) / 256, 256>>>(x, (const int*)ei);
    k_hist<<<(NE + 255) / 256, 256>>>(ei);
    int nb = (NN + 1023) / 1024;   // 98
    k_scan_local<<<nb, 1024>>>();
    k_scan_part<<<1, 32>>>(nb);
    k_finalize<<<(NN + 255) / 256, 256>>>();
    k_scatter<<<(NE + 255) / 256, 256>>>(ei);

    const int WPB = 8;                        // warps (rows) per block
    int grid = (NN + WPB - 1) / WPB;          // 12500
    // SSG hops: out = 0.1*x + 0.3*(A x + A^2 x + A^3 x)
    k_spmm<2, 1><<<grid, WPB * 32>>>(x);      // xh -> h1, acc = 0.1x + 0.3 sum
    k_spmm<0, 2><<<grid, WPB * 32>>>(x);      // h1 -> h2, acc += 0.3 sum
    k_spmm<1, 3><<<grid, WPB * 32>>>(x);      // h2 -> relu(acc) -> g_ach (fp16)
    // mean conv on relu(acc) + residual + relu
    k_mean<<<grid, WPB * 32>>>(x, out);
}

// round 5
// speedup vs baseline: 1.4019x; 1.0851x over previous
#include <cuda_runtime.h>
#include <cuda_fp16.h>
#include <cstdint>

#define NN   100000
#define NE   1600000
#define ALPHA_C 0.1f
#define COEF_C  0.3f            // (1-ALPHA)/K = 0.9/3

// ---------------- scratch (device globals: no allocation allowed) ----------------
__device__ int   g_is64;             // 1 if edge_index is int64, 0 if int32
__device__ int   g_cnt[NN];          // in-degree (original edges)
__device__ int   g_rowptr[NN + 1];   // CSR row pointers by dst
__device__ int   g_cursor[NN];       // scatter cursors
__device__ float g_dinv[NN];         // 1/sqrt(deg+1)
__device__ int   g_part[128];        // scan partials (98 blocks)
__device__ int2  g_sw[NE];           // CSR: {src, w-bits} sorted by dst
__device__ uint2 g_xh [NN * 16];     // x   in fp16 (row = 16 uint2 = 128B)
__device__ uint2 g_h1 [NN * 16];
__device__ uint2 g_h2 [NN * 16];
__device__ uint2 g_ach[NN * 16];     // relu(acc) in fp16 (for mean pass)
__device__ float g_acc[NN * 64];     // fp32 accumulator

// ---------------- convert x -> fp16, zero counters, detect edge dtype ----------------
__global__ void k_prep(const float* __restrict__ x, const int* __restrict__ ei32) {
    int i = blockIdx.x * blockDim.x + threadIdx.x;
    if (i < NN * 16) {
        float4 v = ((const float4*)x)[i];
        __half2 h0 = __floats2half2_rn(v.x, v.y);
        __half2 h1 = __floats2half2_rn(v.z, v.w);
        uint2 u;
        u.x = *(unsigned*)&h0;
        u.y = *(unsigned*)&h1;
        g_xh[i] = u;
    }
    if (i < NN) g_cnt[i] = 0;
    if (i == 0) {
        // int64 little-endian with values < 100000 -> every odd 32-bit word is 0
        int zeros = 0;
        #pragma unroll 1
        for (int k = 1; k < 129; k += 2) zeros += (ei32[k] == 0);
        g_is64 = (zeros >= 60) ? 1 : 0;
    }
}

__device__ __forceinline__ int edge_at(const void* ei, long long idx, int is64) {
    if (is64) return (int)((const long long*)ei)[idx];
    return ((const int*)ei)[idx];
}

// ---------------- CSR build ----------------
__global__ void k_hist(const void* __restrict__ ei) {
    int e = blockIdx.x * blockDim.x + threadIdx.x;
    int is64 = g_is64;
    if (e < NE) {
        int dst = edge_at(ei, (long long)NE + e, is64);
        atomicAdd(&g_cnt[dst], 1);
    }
}

__global__ void k_scan_local() {
    __shared__ int s[1024];
    int tid = threadIdx.x;
    int i = blockIdx.x * 1024 + tid;
    int v = (i < NN) ? g_cnt[i] : 0;
    s[tid] = v;
    __syncthreads();
    #pragma unroll
    for (int off = 1; off < 1024; off <<= 1) {
        int t = (tid >= off) ? s[tid - off] : 0;
        __syncthreads();
        s[tid] += t;
        __syncthreads();
    }
    if (i < NN) g_rowptr[i] = s[tid] - v;   // local exclusive
    if (tid == 1023) g_part[blockIdx.x] = s[1023];
}

// parallel scan of the 98 block partials (was serial: 6-8us -> ~1us)
__global__ void k_scan_part(int nb) {
    __shared__ int s[128];
    int tid = threadIdx.x;
    int v = (tid < nb) ? g_part[tid] : 0;
    s[tid] = v;
    __syncthreads();
    #pragma unroll
    for (int off = 1; off < 128; off <<= 1) {
        int t = (tid >= off) ? s[tid - off] : 0;
        __syncthreads();
        s[tid] += t;
        __syncthreads();
    }
    if (tid < nb) g_part[tid] = s[tid] - v;  // exclusive
    if (tid == nb - 1) g_rowptr[NN] = s[tid];
}

__global__ void k_finalize() {
    int i = blockIdx.x * blockDim.x + threadIdx.x;
    if (i < NN) {
        int rp = g_rowptr[i] + g_part[i >> 10];
        g_rowptr[i] = rp;
        g_cursor[i] = rp;
        g_dinv[i] = rsqrtf((float)(g_cnt[i] + 1));   // +1 self loop
    }
}

__global__ void k_scatter(const void* __restrict__ ei) {
    int e = blockIdx.x * blockDim.x + threadIdx.x;
    int is64 = g_is64;
    if (e < NE) {
        int src = edge_at(ei, e, is64);
        int dst = edge_at(ei, (long long)NE + e, is64);
        int pos = atomicAdd(&g_cursor[dst], 1);
        float w = g_dinv[src] * g_dinv[dst];
        g_sw[pos] = make_int2(src, __float_as_int(w));
    }
}

// ---------------- propagation: warp = 2 half-warps, 2 edges per iteration ----------
// Each 16-lane half gathers one full 128B fp16 row (uint2 = 4 features per lane).
// 1 index LDG.64 + 1 gather LDG.64 per 2 edges => ~1 LDG per edge.
// IN: 0 = g_h1, 1 = g_h2, 2 = g_xh
// PASS: 1 = init acc (0.1x + 0.3 sum), write h1
//       2 = acc += 0.3 sum, write h2
//       3 = acc += 0.3 sum, relu -> g_ach (fp16); no hout
template <int IN, int PASS>
__global__ void k_spmm(const float* __restrict__ x) {
    int row  = blockIdx.x * (blockDim.x >> 5) + (threadIdx.x >> 5);
    if (row >= NN) return;
    int lane = threadIdx.x & 31;
    int sub  = lane >> 4;       // which edge of the pair
    int l    = lane & 15;       // uint2 index within row

    const uint2* hin = (IN == 0) ? g_h1 : (IN == 1) ? g_h2 : g_xh;

    int beg = g_rowptr[row];
    int end = g_rowptr[row + 1];
    float dv = g_dinv[row];

    // self-loop term dinv^2 * h[row]: count once (sub 0 only)
    uint2 sv = __ldg(&hin[row * 16 + l]);
    float2 f0 = __half22float2(*(__half2*)&sv.x);
    float2 f1 = __half22float2(*(__half2*)&sv.y);
    float sw = sub ? 0.f : dv * dv;
    float a0 = sw * f0.x, a1 = sw * f0.y, a2 = sw * f1.x, a3 = sw * f1.y;

    for (int e = beg; e < end; e += 2) {
        int ee = e + sub;
        int2 p = (ee < end) ? __ldg(&g_sw[ee]) : make_int2(row, 0);  // w = 0.0f
        float w = __int_as_float(p.y);
        uint2 v = __ldg(&hin[p.x * 16 + l]);
        float2 v0 = __half22float2(*(__half2*)&v.x);
        float2 v1 = __half22float2(*(__half2*)&v.y);
        a0 += w * v0.x; a1 += w * v0.y; a2 += w * v1.x; a3 += w * v1.y;
    }

    // combine the two half-warp partials
    a0 += __shfl_xor_sync(0xffffffffu, a0, 16);
    a1 += __shfl_xor_sync(0xffffffffu, a1, 16);
    a2 += __shfl_xor_sync(0xffffffffu, a2, 16);
    a3 += __shfl_xor_sync(0xffffffffu, a3, 16);

    if (sub == 0) {
        int o = row * 16 + l;
        if (PASS != 3) {
            __half2 h0 = __floats2half2_rn(a0, a1);
            __half2 h1 = __floats2half2_rn(a2, a3);
            uint2 u; u.x = *(unsigned*)&h0; u.y = *(unsigned*)&h1;
            ((PASS == 1) ? g_h1 : g_h2)[o] = u;
        }

        float4 a;
        if (PASS == 1) {
            float4 xf = __ldg(&((const float4*)x)[o]);
            a.x = ALPHA_C * xf.x; a.y = ALPHA_C * xf.y;
            a.z = ALPHA_C * xf.z; a.w = ALPHA_C * xf.w;
        } else {
            a = ((float4*)g_acc)[o];
        }
        a.x += COEF_C * a0; a.y += COEF_C * a1;
        a.z += COEF_C * a2; a.w += COEF_C * a3;

        if (PASS == 3) {
            __half2 h0 = __floats2half2_rn(fmaxf(a.x, 0.f), fmaxf(a.y, 0.f));
            __half2 h1 = __floats2half2_rn(fmaxf(a.z, 0.f), fmaxf(a.w, 0.f));
            uint2 u; u.x = *(unsigned*)&h0; u.y = *(unsigned*)&h1;
            g_ach[o] = u;
        } else {
            ((float4*)g_acc)[o] = a;
        }
    }
}

// mean conv over original edges on relu(acc) (pre-relu'd fp16), + residual + relu
__global__ void k_mean(const float* __restrict__ x, float* __restrict__ out) {
    int row  = blockIdx.x * (blockDim.x >> 5) + (threadIdx.x >> 5);
    if (row >= NN) return;
    int lane = threadIdx.x & 31;
    int sub  = lane >> 4;
    int l    = lane & 15;

    int beg = g_rowptr[row];
    int end = g_rowptr[row + 1];

    float a0 = 0.f, a1 = 0.f, a2 = 0.f, a3 = 0.f;
    for (int e = beg; e < end; e += 2) {
        int ee = e + sub;
        int2 p = (ee < end) ? __ldg(&g_sw[ee]) : make_int2(row, 0);
        float m = (ee < end) ? 1.f : 0.f;
        uint2 v = __ldg(&g_ach[p.x * 16 + l]);
        float2 v0 = __half22float2(*(__half2*)&v.x);
        float2 v1 = __half22float2(*(__half2*)&v.y);
        a0 += m * v0.x; a1 += m * v0.y; a2 += m * v1.x; a3 += m * v1.y;
    }

    a0 += __shfl_xor_sync(0xffffffffu, a0, 16);
    a1 += __shfl_xor_sync(0xffffffffu, a1, 16);
    a2 += __shfl_xor_sync(0xffffffffu, a2, 16);
    a3 += __shfl_xor_sync(0xffffffffu, a3, 16);

    if (sub == 0) {
        float inv = 1.0f / fmaxf((float)(end - beg), 1.0f);
        int o = row * 16 + l;
        float4 xx = __ldg(&((const float4*)x)[o]);
        float4 r;
        r.x = fmaxf(a0 * inv + xx.x, 0.f);
        r.y = fmaxf(a1 * inv + xx.y, 0.f);
        r.z = fmaxf(a2 * inv + xx.z, 0.f);
        r.w = fmaxf(a3 * inv + xx.w, 0.f);
        ((float4*)out)[o] = r;
    }
}

// ---------------- launch ----------------
extern "C" void kernel_launch(void* const* d_in, const int* in_sizes, int n_in,
                              void* d_out, int out_size) {
    const float* x  = (const float*)d_in[0];
    const void*  ei = (const void*)d_in[1];
    float* out = (float*)d_out;

    k_prep<<<(NN * 16 + 255) / 256, 256>>>(x, (const int*)ei);
    k_hist<<<(NE + 255) / 256, 256>>>(ei);
    int nb = (NN + 1023) / 1024;   // 98
    k_scan_local<<<nb, 1024>>>();
    k_scan_part<<<1, 128>>>(nb);
    k_finalize<<<(NN + 255) / 256, 256>>>();
    k_scatter<<<(NE + 255) / 256, 256>>>(ei);

    const int WPB = 8;                        // warps (rows) per block
    int grid = (NN + WPB - 1) / WPB;          // 12500
    // SSG hops: out = 0.1*x + 0.3*(A x + A^2 x + A^3 x)
    k_spmm<2, 1><<<grid, WPB * 32>>>(x);      // xh -> h1, acc = 0.1x + 0.3 sum
    k_spmm<0, 2><<<grid, WPB * 32>>>(x);      // h1 -> h2, acc += 0.3 sum
    k_spmm<1, 3><<<grid, WPB * 32>>>(x);      // h2 -> relu(acc) -> g_ach
    // mean conv on relu(acc) + residual + relu
    k_mean<<<grid, WPB * 32>>>(x, out);
}

// round 6
// speedup vs baseline: 1.4656x; 1.0454x over previous
#include <cuda_runtime.h>
#include <cuda_fp16.h>
#include <cstdint>

#define NN   100000
#define NE   1600000
#define ALPHA_C 0.1f
#define COEF_C  0.3f            // (1-ALPHA)/K = 0.9/3

// ---------------- scratch (device globals: no allocation allowed) ----------------
__device__ int   g_is64;             // 1 if edge_index is int64, 0 if int32
__device__ int   g_cnt[NN];          // in-degree (original edges)
__device__ int   g_rowptr[NN + 1];   // CSR row pointers by dst
__device__ int   g_cursor[NN];       // scatter cursors
__device__ float g_dinv[NN];         // 1/sqrt(deg+1)
__device__ int   g_part[128];        // scan partials (98 blocks)
__device__ int   g_src[NE];          // CSR: src per edge (sorted by dst), 4B
__device__ uint4 g_xh [NN * 8];      // dinv*x  in fp16 (row = 8 uint4 = 128B)
__device__ uint4 g_h1 [NN * 8];      // dinv*h  in fp16
__device__ uint4 g_h2 [NN * 8];
__device__ uint4 g_ach[NN * 8];      // relu(acc) in fp16 (for mean pass)
__device__ float g_acc[NN * 64];     // fp32 accumulator

// ---------------- fp16 pack/unpack helpers ----------------
__device__ __forceinline__ void unpack8(uint4 v, float* f) {
    float2 t;
    t = __half22float2(*(__half2*)&v.x); f[0] = t.x; f[1] = t.y;
    t = __half22float2(*(__half2*)&v.y); f[2] = t.x; f[3] = t.y;
    t = __half22float2(*(__half2*)&v.z); f[4] = t.x; f[5] = t.y;
    t = __half22float2(*(__half2*)&v.w); f[6] = t.x; f[7] = t.y;
}
__device__ __forceinline__ uint4 pack8(const float* f) {
    uint4 u; __half2 h;
    h = __floats2half2_rn(f[0], f[1]); u.x = *(unsigned*)&h;
    h = __floats2half2_rn(f[2], f[3]); u.y = *(unsigned*)&h;
    h = __floats2half2_rn(f[4], f[5]); u.z = *(unsigned*)&h;
    h = __floats2half2_rn(f[6], f[7]); u.w = *(unsigned*)&h;
    return u;
}

// ---------------- prep: zero counters, detect edge dtype ----------------
__global__ void k_prep(const int* __restrict__ ei32) {
    int i = blockIdx.x * blockDim.x + threadIdx.x;
    if (i < NN) g_cnt[i] = 0;
    if (i == 0) {
        // int64 little-endian with values < 100000 -> every odd 32-bit word is 0
        int zeros = 0;
        #pragma unroll 1
        for (int k = 1; k < 129; k += 2) zeros += (ei32[k] == 0);
        g_is64 = (zeros >= 60) ? 1 : 0;
        g_rowptr[NN] = NE;
    }
}

__device__ __forceinline__ int edge_at(const void* ei, long long idx, int is64) {
    if (is64) return (int)((const long long*)ei)[idx];
    return ((const int*)ei)[idx];
}

// ---------------- CSR build ----------------
__global__ void k_hist(const void* __restrict__ ei) {
    int e = blockIdx.x * blockDim.x + threadIdx.x;
    int is64 = g_is64;
    if (e < NE) {
        int dst = edge_at(ei, (long long)NE + e, is64);
        atomicAdd(&g_cnt[dst], 1);
    }
}

__global__ void k_scan_local() {
    __shared__ int s[1024];
    int tid = threadIdx.x;
    int i = blockIdx.x * 1024 + tid;
    int v = (i < NN) ? g_cnt[i] : 0;
    s[tid] = v;
    __syncthreads();
    #pragma unroll
    for (int off = 1; off < 1024; off <<= 1) {
        int t = (tid >= off) ? s[tid - off] : 0;
        __syncthreads();
        s[tid] += t;
        __syncthreads();
    }
    if (i < NN) g_rowptr[i] = s[tid] - v;   // local exclusive
    if (tid == 1023) g_part[blockIdx.x] = s[1023];
}

// finalize: re-scan the 98 partials per block (cheap), fix rowptr/cursor/dinv,
// AND convert x -> fp16 pre-scaled by dinv[row].  grid = NN*8 threads.
__global__ void k_finalize(const float* __restrict__ x) {
    __shared__ int sp[256];
    int tid = threadIdx.x;
    int pv = (tid < 98) ? g_part[tid] : 0;
    sp[tid] = pv;
    __syncthreads();
    #pragma unroll
    for (int off = 1; off < 256; off <<= 1) {
        int t = (tid >= off) ? sp[tid - off] : 0;
        __syncthreads();
        sp[tid] += t;
        __syncthreads();
    }
    int excl = sp[tid] - pv;   // exclusive prefix
    __syncthreads();
    sp[tid] = excl;
    __syncthreads();

    int j = blockIdx.x * blockDim.x + threadIdx.x;
    if (j < NN) {
        int rp = g_rowptr[j] + sp[j >> 10];
        g_rowptr[j] = rp;
        g_cursor[j] = rp;
        g_dinv[j] = rsqrtf((float)(g_cnt[j] + 1));   // +1 self loop
    }
    if (j < NN * 8) {
        int row = j >> 3;
        float dv = rsqrtf((float)(__ldg(&g_cnt[row]) + 1));
        float4 p0 = __ldg(&((const float4*)x)[j * 2]);
        float4 p1 = __ldg(&((const float4*)x)[j * 2 + 1]);
        float f[8] = { dv*p0.x, dv*p0.y, dv*p0.z, dv*p0.w,
                       dv*p1.x, dv*p1.y, dv*p1.z, dv*p1.w };
        g_xh[j] = pack8(f);
    }
}

__global__ void k_scatter(const void* __restrict__ ei) {
    int e = blockIdx.x * blockDim.x + threadIdx.x;
    int is64 = g_is64;
    if (e < NE) {
        int src = edge_at(ei, e, is64);
        int dst = edge_at(ei, (long long)NE + e, is64);
        int pos = atomicAdd(&g_cursor[dst], 1);
        g_src[pos] = src;
    }
}

// ---------------- propagation: warp = 4 x 8-lane groups, 4 edges/iter ----------
// Rows are pre-scaled: stored v = dinv*h.  t = sum_src v[src] + v[row];
// h_new = dinv*t, stored v_new = dinv^2*t, acc += COEF*dinv*t.
// IN: 0 = g_h1, 1 = g_h2, 2 = g_xh
// PASS: 1 = init acc (0.1x + 0.3*dv*t), write h1
//       2 = acc += 0.3*dv*t, write h2
//       3 = acc += 0.3*dv*t, relu -> g_ach (fp16); no hout
template <int IN, int PASS>
__global__ void k_spmm(const float* __restrict__ x) {
    int row  = blockIdx.x * (blockDim.x >> 5) + (threadIdx.x >> 5);
    if (row >= NN) return;
    int lane = threadIdx.x & 31;
    int sub  = lane >> 3;       // edge slot 0..3
    int l    = lane & 7;        // uint4 index within 128B row

    const uint4* hin = (IN == 0) ? g_h1 : (IN == 1) ? g_h2 : g_xh;

    int beg = g_rowptr[row];
    int end = g_rowptr[row + 1];
    float dv = g_dinv[row];

    float a[8];
    {   // self term: + v[row], counted once (sub 0)
        uint4 sv = __ldg(&hin[row * 8 + l]);
        float f[8]; unpack8(sv, f);
        float m0 = (sub == 0) ? 1.f : 0.f;
        #pragma unroll
        for (int i = 0; i < 8; i++) a[i] = m0 * f[i];
    }

    // depth-2 pipelined: next indices load while current gather is in flight
    int e  = beg;
    int ee = e + sub;
    int s  = (ee < end) ? __ldg(&g_src[ee]) : row;
    float m = (ee < end) ? 1.f : 0.f;
    while (e < end) {
        int en = e + 4;
        int s2 = row; float m2 = 0.f;
        int ee2 = en + sub;
        if (ee2 < end) { s2 = __ldg(&g_src[ee2]); m2 = 1.f; }
        uint4 v = __ldg(&hin[s * 8 + l]);
        float f[8]; unpack8(v, f);
        #pragma unroll
        for (int i = 0; i < 8; i++) a[i] = fmaf(m, f[i], a[i]);
        s = s2; m = m2; e = en;
    }

    #pragma unroll
    for (int i = 0; i < 8; i++) {
        a[i] += __shfl_xor_sync(0xffffffffu, a[i], 8);
        a[i] += __shfl_xor_sync(0xffffffffu, a[i], 16);
    }

    if (sub == 0) {
        int o = row * 8 + l;
        if (PASS != 3) {
            float hv[8]; float dv2 = dv * dv;
            #pragma unroll
            for (int i = 0; i < 8; i++) hv[i] = dv2 * a[i];
            ((PASS == 1) ? g_h1 : g_h2)[o] = pack8(hv);
        }

        float accv[8];
        float cdv = COEF_C * dv;
        if (PASS == 1) {
            float4 x0 = __ldg(&((const float4*)x)[o * 2]);
            float4 x1 = __ldg(&((const float4*)x)[o * 2 + 1]);
            float xf[8] = { x0.x, x0.y, x0.z, x0.w, x1.x, x1.y, x1.z, x1.w };
            #pragma unroll
            for (int i = 0; i < 8; i++) accv[i] = ALPHA_C * xf[i] + cdv * a[i];
        } else {
            float4 a0 = ((float4*)g_acc)[o * 2];
            float4 a1 = ((float4*)g_acc)[o * 2 + 1];
            float ap[8] = { a0.x, a0.y, a0.z, a0.w, a1.x, a1.y, a1.z, a1.w };
            #pragma unroll
            for (int i = 0; i < 8; i++) accv[i] = ap[i] + cdv * a[i];
        }

        if (PASS == 3) {
            float rv[8];
            #pragma unroll
            for (int i = 0; i < 8; i++) rv[i] = fmaxf(accv[i], 0.f);
            g_ach[o] = pack8(rv);
        } else {
            float4 w0 = make_float4(accv[0], accv[1], accv[2], accv[3]);
            float4 w1 = make_float4(accv[4], accv[5], accv[6], accv[7]);
            ((float4*)g_acc)[o * 2]     = w0;
            ((float4*)g_acc)[o * 2 + 1] = w1;
        }
    }
}

// mean conv over original edges on relu(acc) (pre-relu'd fp16) + residual + relu
__global__ void k_mean(const float* __restrict__ x, float* __restrict__ out) {
    int row  = blockIdx.x * (blockDim.x >> 5) + (threadIdx.x >> 5);
    if (row >= NN) return;
    int lane = threadIdx.x & 31;
    int sub  = lane >> 3;
    int l    = lane & 7;

    int beg = g_rowptr[row];
    int end = g_rowptr[row + 1];

    float a[8] = {0.f, 0.f, 0.f, 0.f, 0.f, 0.f, 0.f, 0.f};

    int e  = beg;
    int ee = e + sub;
    int s  = (ee < end) ? __ldg(&g_src[ee]) : row;
    float m = (ee < end) ? 1.f : 0.f;
    while (e < end) {
        int en = e + 4;
        int s2 = row; float m2 = 0.f;
        int ee2 = en + sub;
        if (ee2 < end) { s2 = __ldg(&g_src[ee2]); m2 = 1.f; }
        uint4 v = __ldg(&g_ach[s * 8 + l]);
        float f[8]; unpack8(v, f);
        #pragma unroll
        for (int i = 0; i < 8; i++) a[i] = fmaf(m, f[i], a[i]);
        s = s2; m = m2; e = en;
    }

    #pragma unroll
    for (int i = 0; i < 8; i++) {
        a[i] += __shfl_xor_sync(0xffffffffu, a[i], 8);
        a[i] += __shfl_xor_sync(0xffffffffu, a[i], 16);
    }

    if (sub == 0) {
        float inv = 1.0f / fmaxf((float)(end - beg), 1.0f);
        int o = row * 8 + l;
        float4 x0 = __ldg(&((const float4*)x)[o * 2]);
        float4 x1 = __ldg(&((const float4*)x)[o * 2 + 1]);
        float4 r0, r1;
        r0.x = fmaxf(a[0] * inv + x0.x, 0.f);
        r0.y = fmaxf(a[1] * inv + x0.y, 0.f);
        r0.z = fmaxf(a[2] * inv + x0.z, 0.f);
        r0.w = fmaxf(a[3] * inv + x0.w, 0.f);
        r1.x = fmaxf(a[4] * inv + x1.x, 0.f);
        r1.y = fmaxf(a[5] * inv + x1.y, 0.f);
        r1.z = fmaxf(a[6] * inv + x1.z, 0.f);
        r1.w = fmaxf(a[7] * inv + x1.w, 0.f);
        ((float4*)out)[o * 2]     = r0;
        ((float4*)out)[o * 2 + 1] = r1;
    }
}

// ---------------- launch ----------------
extern "C" void kernel_launch(void* const* d_in, const int* in_sizes, int n_in,
                              void* d_out, int out_size) {
    const float* x  = (const float*)d_in[0];
    const void*  ei = (const void*)d_in[1];
    float* out = (float*)d_out;

    k_prep<<<(NN + 255) / 256, 256>>>((const int*)ei);
    k_hist<<<(NE + 255) / 256, 256>>>(ei);
    int nb = (NN + 1023) / 1024;   // 98
    k_scan_local<<<nb, 1024>>>();
    k_finalize<<<(NN * 8 + 255) / 256, 256>>>(x);
    k_scatter<<<(NE + 255) / 256, 256>>>(ei);

    const int WPB = 8;                        // warps (rows) per block
    int grid = (NN + WPB - 1) / WPB;          // 12500
    // SSG hops: out = 0.1*x + 0.3*(A x + A^2 x + A^3 x)
    k_spmm<2, 1><<<grid, WPB * 32>>>(x);      // xh -> h1, acc = 0.1x + 0.3 dv t
    k_spmm<0, 2><<<grid, WPB * 32>>>(x);      // h1 -> h2, acc += 0.3 dv t
    k_spmm<1, 3><<<grid, WPB * 32>>>(x);      // h2 -> relu(acc) -> g_ach
    // mean conv on relu(acc) + residual + relu
    k_mean<<<grid, WPB * 32>>>(x, out);
}